// round 2
// baseline (speedup 1.0000x reference)
#include <cuda_runtime.h>
#include <math.h>

// Problem constants
#define T_SEQ   2048
#define DIM     1024
#define NH      16
#define HD      64
#define QKV3    3072
#define NB      2
#define MROWS   (NB * T_SEQ)     // 4096
#define CHUNK   64
#define NCHUNK  (T_SEQ / CHUNK)  // 32

typedef unsigned long long ull;

// ---- packed f32x2 helpers (B300: full fp32 rate only via fma.rn.f32x2) ----
__device__ __forceinline__ ull pack2(float lo, float hi) {
    ull r;
    asm("mov.b64 %0, {%1, %2};" : "=l"(r) : "f"(lo), "f"(hi));
    return r;
}
__device__ __forceinline__ float2 unpack2(ull v) {
    float2 f;
    asm("mov.b64 {%0, %1}, %2;" : "=f"(f.x), "=f"(f.y) : "l"(v));
    return f;
}
__device__ __forceinline__ void fma2(ull& d, ull a, ull b) {
    asm("fma.rn.f32x2 %0, %1, %2, %0;" : "+l"(d) : "l"(a), "l"(b));
}
__device__ __forceinline__ void mul2(ull& d, ull a) {
    asm("mul.rn.f32x2 %0, %0, %1;" : "+l"(d) : "l"(a));
}

// Scratch (device globals: allocation-free per harness rules)
__device__ __align__(16) float g_qkv[(size_t)NB * T_SEQ * QKV3];   // 48 MiB
__device__ __align__(16) float g_attn[(size_t)NB * T_SEQ * DIM];   // 16 MiB

// ---------------------------------------------------------------------------
// GEMM: C[M,N] = A[M,K] @ B[N,K]^T. 128x128 tile, BK=16, 256 threads,
// 8x8 micro-tile per thread, accumulators packed pairwise along j (f32x2).
// ---------------------------------------------------------------------------
__global__ __launch_bounds__(256) void gemm_abT(
    const float* __restrict__ A, const float* __restrict__ B,
    float* __restrict__ C, int M, int N, int K)
{
    __shared__ __align__(16) float As[16 * 132];
    __shared__ __align__(16) float Bs[16 * 132];

    const int tid = threadIdx.x;
    const int ty = tid >> 4;
    const int tx = tid & 15;
    const int row0 = blockIdx.y * 128;
    const int col0 = blockIdx.x * 128;

    ull acc2[8][4];
#pragma unroll
    for (int i = 0; i < 8; i++)
#pragma unroll
        for (int j = 0; j < 4; j++) acc2[i][j] = 0ull;  // (0.f, 0.f)

    for (int k0 = 0; k0 < K; k0 += 16) {
#pragma unroll
        for (int it = 0; it < 2; it++) {
            const int idx = tid + it * 256;       // 0..511
            const int m  = idx >> 2;              // 0..127
            const int kg = idx & 3;               // k group of 4
            const float4 va = *(const float4*)(A + (size_t)(row0 + m) * K + k0 + 4 * kg);
            As[(4 * kg + 0) * 132 + m] = va.x;
            As[(4 * kg + 1) * 132 + m] = va.y;
            As[(4 * kg + 2) * 132 + m] = va.z;
            As[(4 * kg + 3) * 132 + m] = va.w;
            const float4 vb = *(const float4*)(B + (size_t)(col0 + m) * K + k0 + 4 * kg);
            Bs[(4 * kg + 0) * 132 + m] = vb.x;
            Bs[(4 * kg + 1) * 132 + m] = vb.y;
            Bs[(4 * kg + 2) * 132 + m] = vb.z;
            Bs[(4 * kg + 3) * 132 + m] = vb.w;
        }
        __syncthreads();

#pragma unroll
        for (int kk = 0; kk < 16; kk++) {
            const float4 a0 = *(const float4*)(As + kk * 132 + 8 * ty);
            const float4 a1 = *(const float4*)(As + kk * 132 + 8 * ty + 4);
            const float4 b0 = *(const float4*)(Bs + kk * 132 + 8 * tx);
            const float4 b1 = *(const float4*)(Bs + kk * 132 + 8 * tx + 4);
            const ull bp[4] = {pack2(b0.x, b0.y), pack2(b0.z, b0.w),
                               pack2(b1.x, b1.y), pack2(b1.z, b1.w)};
            const float av[8] = {a0.x, a0.y, a0.z, a0.w, a1.x, a1.y, a1.z, a1.w};
#pragma unroll
            for (int i = 0; i < 8; i++) {
                const ull ad = pack2(av[i], av[i]);   // broadcast pair (1 MOV)
#pragma unroll
                for (int j = 0; j < 4; j++) fma2(acc2[i][j], ad, bp[j]);
            }
        }
        __syncthreads();
    }

#pragma unroll
    for (int i = 0; i < 8; i++) {
        const float2 p0 = unpack2(acc2[i][0]);
        const float2 p1 = unpack2(acc2[i][1]);
        const float2 p2 = unpack2(acc2[i][2]);
        const float2 p3 = unpack2(acc2[i][3]);
        float* cp = C + (size_t)(row0 + 8 * ty + i) * N + col0 + 8 * tx;
        *(float4*)(cp)     = make_float4(p0.x, p0.y, p1.x, p1.y);
        *(float4*)(cp + 4) = make_float4(p2.x, p2.y, p3.x, p3.y);
    }
}

// ---------------------------------------------------------------------------
// Flash attention over 64x64 tiles. Mask (causal | same_chunk, chunk=64) is
// exactly block-lower-triangular at 64 granularity with FULL diagonal blocks:
// query chunk qc attends to key chunks 0..qc with no element masking.
// Block = (qc, h, b), 256 threads as 16x16, 4x4 patch per thread, f32x2 FMAs.
// ---------------------------------------------------------------------------
#define QS_STR 68   // 64 + 4 pad

__global__ __launch_bounds__(256) void attn_kernel(
    const float* __restrict__ qkv, float* __restrict__ out)
{
    extern __shared__ __align__(16) float sm[];
    float* Qs = sm;                    // [64 d][QS_STR] (row-minor)
    float* Ks = Qs + 64 * QS_STR;      // [64 d][QS_STR] (key-minor)
    float* Vs = Ks + 64 * QS_STR;      // [64 key][QS_STR] (d-minor)
    float* Ps = Vs + 64 * QS_STR;      // [64 row][QS_STR] (key-minor)

    const int tid = threadIdx.x;
    const int ty = tid >> 4;
    const int tx = tid & 15;
    const int qc = blockIdx.x;
    const int h  = blockIdx.y;
    const int b  = blockIdx.z;

    const size_t base = (size_t)b * T_SEQ * QKV3 + (size_t)h * HD;

    // Load Q tile transposed: Qs[d][r]
#pragma unroll
    for (int it = 0; it < 4; it++) {
        const int idx = tid + it * 256;
        const int r  = idx >> 4;
        const int dg = idx & 15;
        const float4 v = *(const float4*)(qkv + base + (size_t)(qc * 64 + r) * QKV3 + 4 * dg);
        Qs[(4 * dg + 0) * QS_STR + r] = v.x;
        Qs[(4 * dg + 1) * QS_STR + r] = v.y;
        Qs[(4 * dg + 2) * QS_STR + r] = v.z;
        Qs[(4 * dg + 3) * QS_STR + r] = v.w;
    }

    ull accv2[4][2];     // O accumulator, pairs along d-within-patch
    float mrow[4], lrow[4];
#pragma unroll
    for (int i = 0; i < 4; i++) {
        mrow[i] = -1e30f; lrow[i] = 0.f;
        accv2[i][0] = 0ull; accv2[i][1] = 0ull;
    }

    for (int kc = 0; kc <= qc; kc++) {
        __syncthreads();
#pragma unroll
        for (int it = 0; it < 4; it++) {
            const int idx = tid + it * 256;
            const int r  = idx >> 4;
            const int dg = idx & 15;
            const float* rowp = qkv + base + (size_t)(kc * 64 + r) * QKV3;
            const float4 kv = *(const float4*)(rowp + DIM + 4 * dg);
            Ks[(4 * dg + 0) * QS_STR + r] = kv.x;
            Ks[(4 * dg + 1) * QS_STR + r] = kv.y;
            Ks[(4 * dg + 2) * QS_STR + r] = kv.z;
            Ks[(4 * dg + 3) * QS_STR + r] = kv.w;
            const float4 vv = *(const float4*)(rowp + 2 * DIM + 4 * dg);
            *(float4*)(Vs + r * QS_STR + 4 * dg) = vv;
        }
        __syncthreads();

        // S = Q K^T (pairs along key-column)
        ull s2[4][2];
#pragma unroll
        for (int i = 0; i < 4; i++) { s2[i][0] = 0ull; s2[i][1] = 0ull; }

#pragma unroll 8
        for (int d = 0; d < 64; d++) {
            const float4 qa = *(const float4*)(Qs + d * QS_STR + 4 * ty);
            const float4 kb = *(const float4*)(Ks + d * QS_STR + 4 * tx);
            const ull kp0 = pack2(kb.x, kb.y);
            const ull kp1 = pack2(kb.z, kb.w);
            const float qv[4] = {qa.x, qa.y, qa.z, qa.w};
#pragma unroll
            for (int i = 0; i < 4; i++) {
                const ull qd = pack2(qv[i], qv[i]);
                fma2(s2[i][0], qd, kp0);
                fma2(s2[i][1], qd, kp1);
            }
        }

        // Online softmax per row (16-lane shfl reductions within tx group)
#pragma unroll
        for (int i = 0; i < 4; i++) {
            const float2 sa = unpack2(s2[i][0]);
            const float2 sb = unpack2(s2[i][1]);
            float s0 = sa.x * 0.125f, s1 = sa.y * 0.125f;   // 1/sqrt(64)
            float s2v = sb.x * 0.125f, s3 = sb.y * 0.125f;
            float mx = fmaxf(fmaxf(s0, s1), fmaxf(s2v, s3));
#pragma unroll
            for (int o = 1; o < 16; o <<= 1)
                mx = fmaxf(mx, __shfl_xor_sync(0xffffffffu, mx, o));
            const float mnew = fmaxf(mrow[i], mx);
            const float p0 = __expf(s0 - mnew);
            const float p1 = __expf(s1 - mnew);
            const float p2 = __expf(s2v - mnew);
            const float p3 = __expf(s3 - mnew);
            float rs = p0 + p1 + p2 + p3;
#pragma unroll
            for (int o = 1; o < 16; o <<= 1)
                rs += __shfl_xor_sync(0xffffffffu, rs, o);
            const float alpha = __expf(mrow[i] - mnew);
            const ull alphad = pack2(alpha, alpha);
            mul2(accv2[i][0], alphad);
            mul2(accv2[i][1], alphad);
            lrow[i] = lrow[i] * alpha + rs;
            mrow[i] = mnew;
            *(float4*)(Ps + (4 * ty + i) * QS_STR + 4 * tx) = make_float4(p0, p1, p2, p3);
        }
        __syncthreads();

        // O += P @ V (pairs along d)
#pragma unroll 8
        for (int c = 0; c < 64; c++) {
            const float4 vv = *(const float4*)(Vs + c * QS_STR + 4 * tx);
            const ull vp0 = pack2(vv.x, vv.y);
            const ull vp1 = pack2(vv.z, vv.w);
#pragma unroll
            for (int i = 0; i < 4; i++) {
                const float pr = Ps[(4 * ty + i) * QS_STR + c];
                const ull pd = pack2(pr, pr);
                fma2(accv2[i][0], pd, vp0);
                fma2(accv2[i][1], pd, vp1);
            }
        }
    }

    // Normalize + write: out[b, t, h*64 + d]
#pragma unroll
    for (int i = 0; i < 4; i++) {
        const float inv = 1.f / lrow[i];
        const float2 a0 = unpack2(accv2[i][0]);
        const float2 a1 = unpack2(accv2[i][1]);
        float* op = out + (size_t)(b * T_SEQ + qc * 64 + 4 * ty + i) * DIM + h * HD + 4 * tx;
        *(float4*)op = make_float4(a0.x * inv, a0.y * inv, a1.x * inv, a1.y * inv);
    }
}

// ---------------------------------------------------------------------------
extern "C" void kernel_launch(void* const* d_in, const int* in_sizes, int n_in,
                              void* d_out, int out_size)
{
    (void)in_sizes; (void)n_in; (void)out_size;
    const float* x    = (const float*)d_in[0];   // [2,2048,1024]
    const float* Wqkv = (const float*)d_in[1];   // [3072,1024]
    const float* Wout = (const float*)d_in[2];   // [1024,1024]
    float* out = (float*)d_out;                  // [2,2048,1024]

    float* qkv_p  = nullptr;
    float* attn_p = nullptr;
    cudaGetSymbolAddress((void**)&qkv_p,  g_qkv);
    cudaGetSymbolAddress((void**)&attn_p, g_attn);

    // 1) QKV projection: [4096,3072] = x @ Wqkv^T
    {
        dim3 grid(QKV3 / 128, MROWS / 128);
        gemm_abT<<<grid, 256>>>(x, Wqkv, qkv_p, MROWS, QKV3, DIM);
    }

    // 2) Chunked-causal flash attention (full 64x64 tiles, no element mask)
    {
        const int smem = 4 * 64 * QS_STR * (int)sizeof(float);  // 69,632 B
        cudaFuncSetAttribute(attn_kernel, cudaFuncAttributeMaxDynamicSharedMemorySize, smem);
        dim3 grid(NCHUNK, NH, NB);
        attn_kernel<<<grid, 256, smem>>>(qkv_p, attn_p);
    }

    // 3) Output projection: [4096,1024] = attn @ Wout^T
    {
        dim3 grid(DIM / 128, MROWS / 128);
        gemm_abT<<<grid, 256>>>(attn_p, Wout, out, MROWS, DIM, DIM);
    }
}

// round 7
// speedup vs baseline: 2.7851x; 2.7851x over previous
#include <cuda_runtime.h>
#include <cuda_bf16.h>
#include <cstdint>
#include <math.h>

// Problem constants
#define T_SEQ   2048
#define DIM     1024
#define NH      16
#define HD      64
#define QKV3    3072
#define NB      2
#define MROWS   (NB * T_SEQ)     // 4096
#define NCHUNK  (T_SEQ / 64)     // 32

// ---------------- scratch (device globals; allocation-free) ----------------
__device__ __align__(16) __nv_bfloat16 g_x_hi [(size_t)MROWS * DIM];
__device__ __align__(16) __nv_bfloat16 g_x_lo [(size_t)MROWS * DIM];
__device__ __align__(16) __nv_bfloat16 g_wq_hi[(size_t)QKV3 * DIM];
__device__ __align__(16) __nv_bfloat16 g_wq_lo[(size_t)QKV3 * DIM];
__device__ __align__(16) __nv_bfloat16 g_wo_hi[(size_t)DIM * DIM];
__device__ __align__(16) __nv_bfloat16 g_wo_lo[(size_t)DIM * DIM];
__device__ __align__(16) __nv_bfloat16 g_q3_hi[(size_t)MROWS * QKV3];  // split qkv
__device__ __align__(16) __nv_bfloat16 g_q3_lo[(size_t)MROWS * QKV3];
__device__ __align__(16) __nv_bfloat16 g_a_hi [(size_t)MROWS * DIM];   // split attn out
__device__ __align__(16) __nv_bfloat16 g_a_lo [(size_t)MROWS * DIM];

// ---------------- helpers ----------------
__device__ __forceinline__ uint32_t smem_u32(const void* p) {
    uint32_t a;
    asm("{ .reg .u64 t; cvta.to.shared.u64 t, %1; cvt.u32.u64 %0, t; }" : "=r"(a) : "l"(p));
    return a;
}
__device__ __forceinline__ void cp16(uint32_t dst, const void* src) {
    asm volatile("cp.async.cg.shared.global [%0], [%1], 16;" :: "r"(dst), "l"(src) : "memory");
}
#define CP_COMMIT() asm volatile("cp.async.commit_group;" ::: "memory")
#define CP_WAIT0()  asm volatile("cp.async.wait_group 0;" ::: "memory")

__device__ __forceinline__ void ldm_x4(uint32_t* r, uint32_t addr) {
    asm volatile("ldmatrix.sync.aligned.m8n8.x4.shared.b16 {%0,%1,%2,%3}, [%4];"
                 : "=r"(r[0]), "=r"(r[1]), "=r"(r[2]), "=r"(r[3]) : "r"(addr));
}
__device__ __forceinline__ void ldm_x4_t(uint32_t* r, uint32_t addr) {
    asm volatile("ldmatrix.sync.aligned.m8n8.x4.trans.shared.b16 {%0,%1,%2,%3}, [%4];"
                 : "=r"(r[0]), "=r"(r[1]), "=r"(r[2]), "=r"(r[3]) : "r"(addr));
}
__device__ __forceinline__ void mma_bf16(float* d, const uint32_t* a, const uint32_t* b) {
    asm volatile(
        "mma.sync.aligned.m16n8k16.row.col.f32.bf16.bf16.f32 "
        "{%0,%1,%2,%3}, {%4,%5,%6,%7}, {%8,%9}, {%0,%1,%2,%3};"
        : "+f"(d[0]), "+f"(d[1]), "+f"(d[2]), "+f"(d[3])
        : "r"(a[0]), "r"(a[1]), "r"(a[2]), "r"(a[3]), "r"(b[0]), "r"(b[1]));
}
__device__ __forceinline__ uint32_t pkbf2(float a, float b) {
    __nv_bfloat162 t = __floats2bfloat162_rn(a, b);
    return *(uint32_t*)&t;
}
// split pack: hi = bf16x2(x,y); lo = bf16x2(x-hi.x, y-hi.y)
__device__ __forceinline__ void splitpk(float x, float y, uint32_t& hi, uint32_t& lo) {
    const float hx = __bfloat162float(__float2bfloat16_rn(x));
    const float hy = __bfloat162float(__float2bfloat16_rn(y));
    hi = pkbf2(hx, hy);
    lo = pkbf2(x - hx, y - hy);
}

// ---------------------------------------------------------------------------
// fp32 -> bf16 hi/lo split conversion (inputs only)
// ---------------------------------------------------------------------------
__global__ __launch_bounds__(256) void cvt_split(
    const float4* __restrict__ in, __nv_bfloat16* __restrict__ hi,
    __nv_bfloat16* __restrict__ lo, int n4)
{
    int i = blockIdx.x * 256 + threadIdx.x;
    if (i >= n4) return;
    const float4 v = in[i];
    uint2 h, l;
    splitpk(v.x, v.y, h.x, l.x);
    splitpk(v.z, v.w, h.y, l.y);
    *(uint2*)(hi + 4 * (size_t)i) = h;
    *(uint2*)(lo + 4 * (size_t)i) = l;
}

// ---------------------------------------------------------------------------
// Warp-MMA GEMM: C[M,N] = (Ah+Al)[M,K] @ (Bh+Bl)[N,K]^T, 3-term bf16 split.
// 128x128 CTA tile, BK=32, cp.async double buffer, 8 warps (32x64 each).
// split_out: 0 -> fp32 C; 1 -> bf16 hi/lo split outputs (Chi/Clo).
// ---------------------------------------------------------------------------
#define BM 128
#define BN 128
#define BK 32
#define ASTR 80
#define MAT_B (128 * ASTR)
#define STAGE_B (4 * MAT_B)

__device__ __forceinline__ void stage_mat(
    const __nv_bfloat16* __restrict__ g, int ld, int r0, int k0,
    uint32_t sdst, int tid)
{
#pragma unroll
    for (int it = 0; it < 2; it++) {
        const int idx = tid + it * 256;
        const int r = idx >> 2;
        const int c = idx & 3;
        cp16(sdst + r * ASTR + c * 16, g + (size_t)(r0 + r) * ld + k0 + c * 8);
    }
}

__global__ __launch_bounds__(256) void gemm_mma(
    const __nv_bfloat16* __restrict__ Ah, const __nv_bfloat16* __restrict__ Al,
    const __nv_bfloat16* __restrict__ Bh, const __nv_bfloat16* __restrict__ Bl,
    float* __restrict__ C, __nv_bfloat16* __restrict__ Chi,
    __nv_bfloat16* __restrict__ Clo, int M, int N, int K, int split_out)
{
    extern __shared__ __align__(16) char smem[];
    const uint32_t sb = smem_u32(smem);
    const int tid = threadIdx.x;
    const int wid = tid >> 5;
    const int lane = tid & 31;
    const int warp_m = wid & 3;
    const int warp_n = wid >> 2;
    const int row0 = blockIdx.y * BM;
    const int col0 = blockIdx.x * BN;

    float acc[2][8][4];
#pragma unroll
    for (int mi = 0; mi < 2; mi++)
#pragma unroll
        for (int nj = 0; nj < 8; nj++)
#pragma unroll
            for (int e = 0; e < 4; e++) acc[mi][nj][e] = 0.f;

    stage_mat(Ah, K, row0, 0, sb + 0 * MAT_B, tid);
    stage_mat(Al, K, row0, 0, sb + 1 * MAT_B, tid);
    stage_mat(Bh, K, col0, 0, sb + 2 * MAT_B, tid);
    stage_mat(Bl, K, col0, 0, sb + 3 * MAT_B, tid);
    CP_COMMIT();

    const int NS = K / BK;
    for (int s = 0; s < NS; s++) {
        const int buf = s & 1;
        CP_WAIT0();
        __syncthreads();
        if (s + 1 < NS) {
            const uint32_t nb = sb + (buf ^ 1) * STAGE_B;
            const int k0 = (s + 1) * BK;
            stage_mat(Ah, K, row0, k0, nb + 0 * MAT_B, tid);
            stage_mat(Al, K, row0, k0, nb + 1 * MAT_B, tid);
            stage_mat(Bh, K, col0, k0, nb + 2 * MAT_B, tid);
            stage_mat(Bl, K, col0, k0, nb + 3 * MAT_B, tid);
            CP_COMMIT();
        }

        const uint32_t sAh = sb + buf * STAGE_B + 0 * MAT_B;
        const uint32_t sAl = sb + buf * STAGE_B + 1 * MAT_B;
        const uint32_t sBh = sb + buf * STAGE_B + 2 * MAT_B;
        const uint32_t sBl = sb + buf * STAGE_B + 3 * MAT_B;

#pragma unroll
        for (int ks = 0; ks < 2; ks++) {
            uint32_t ah[2][4], al_[2][4];
#pragma unroll
            for (int mi = 0; mi < 2; mi++) {
                const int m = warp_m * 32 + mi * 16 + (lane & 15);
                const uint32_t off = (uint32_t)m * ASTR + ks * 32 + ((lane >> 4) & 1) * 16;
                ldm_x4(ah[mi], sAh + off);
                ldm_x4(al_[mi], sAl + off);
            }
#pragma unroll
            for (int np = 0; np < 4; np++) {
                const int n = warp_n * 64 + np * 16 + (lane & 7) + ((lane >> 4) & 1) * 8;
                const uint32_t boff = (uint32_t)n * ASTR + ks * 32 + ((lane >> 3) & 1) * 16;
                uint32_t bh[4], bl[4];
                ldm_x4(bh, sBh + boff);
                ldm_x4(bl, sBl + boff);
#pragma unroll
                for (int j = 0; j < 2; j++) {
                    const int nj = np * 2 + j;
#pragma unroll
                    for (int mi = 0; mi < 2; mi++) {
                        mma_bf16(acc[mi][nj], ah[mi],  bh + 2 * j);
                        mma_bf16(acc[mi][nj], ah[mi],  bl + 2 * j);
                        mma_bf16(acc[mi][nj], al_[mi], bh + 2 * j);
                    }
                }
            }
        }
        __syncthreads();
    }

    const int lr = lane >> 2;
    const int lc = (lane & 3) * 2;
#pragma unroll
    for (int mi = 0; mi < 2; mi++) {
#pragma unroll
        for (int nj = 0; nj < 8; nj++) {
            const int r = row0 + warp_m * 32 + mi * 16 + lr;
            const int c = col0 + warp_n * 64 + nj * 8 + lc;
            if (split_out) {
                uint32_t h0, l0, h1, l1;
                splitpk(acc[mi][nj][0], acc[mi][nj][1], h0, l0);
                splitpk(acc[mi][nj][2], acc[mi][nj][3], h1, l1);
                *(uint32_t*)(Chi + (size_t)r * N + c) = h0;
                *(uint32_t*)(Clo + (size_t)r * N + c) = l0;
                *(uint32_t*)(Chi + (size_t)(r + 8) * N + c) = h1;
                *(uint32_t*)(Clo + (size_t)(r + 8) * N + c) = l1;
            } else {
                *(float2*)(C + (size_t)r * N + c) =
                    make_float2(acc[mi][nj][0], acc[mi][nj][1]);
                *(float2*)(C + (size_t)(r + 8) * N + c) =
                    make_float2(acc[mi][nj][2], acc[mi][nj][3]);
            }
        }
    }
}

// ---------------------------------------------------------------------------
// Tensor-core flash attention over 64x64 tiles.
// Mask (causal | same_chunk, 64) == block-lower-triangular with full diagonal
// blocks: query chunk qc attends key chunks 0..qc, NO element masking.
// CTA = (qc,h,b), 4 warps; warp w owns rows 16w..16w+15.
// S = QK^T: 3-term bf16 split.  Softmax in C-fragment registers.
// P -> A-frags by register repack (FA2 identity).  O += PV: 3-term split,
// V B-frags via ldmatrix.trans.  Heavy-first CTA order.
// ---------------------------------------------------------------------------
#define AT_STRB 144            // smem row stride bytes (64 bf16 + 16B pad)
#define AT_MAT  (64 * AT_STRB) // 9216 B per matrix

__global__ __launch_bounds__(128) void attn_mma(
    const __nv_bfloat16* __restrict__ qh_g, const __nv_bfloat16* __restrict__ ql_g,
    __nv_bfloat16* __restrict__ oh_g, __nv_bfloat16* __restrict__ ol_g)
{
    extern __shared__ __align__(16) char smx[];
    const uint32_t sb  = smem_u32(smx);
    const uint32_t sQh = sb,              sQl = sb + 1 * AT_MAT;
    const uint32_t sKh = sb + 2 * AT_MAT, sKl = sb + 3 * AT_MAT;
    const uint32_t sVh = sb + 4 * AT_MAT, sVl = sb + 5 * AT_MAT;

    const int tid = threadIdx.x;
    const int wid = tid >> 5;
    const int lane = tid & 31;
    const int qc = (NCHUNK - 1) - blockIdx.x;   // heavy chunks first
    const int h  = blockIdx.y;
    const int b  = blockIdx.z;

    // stage Q (hi/lo), rows qc*64 + r, cols h*64..+63 of the qkv split arrays
    const size_t rowq = ((size_t)(b * T_SEQ + qc * 64)) * QKV3 + h * HD;
#pragma unroll
    for (int it = 0; it < 4; it++) {
        const int idx = tid + it * 128;
        const int r = idx >> 3, c = idx & 7;
        const size_t g = rowq + (size_t)r * QKV3 + c * 8;
        const uint32_t so = (uint32_t)r * AT_STRB + c * 16;
        cp16(sQh + so, qh_g + g);
        cp16(sQl + so, ql_g + g);
    }
    CP_COMMIT();

    float o[8][4];
    float mrow[2], lrow[2];
#pragma unroll
    for (int n = 0; n < 8; n++)
#pragma unroll
        for (int e = 0; e < 4; e++) o[n][e] = 0.f;
    mrow[0] = mrow[1] = -1e30f;
    lrow[0] = lrow[1] = 0.f;

    CP_WAIT0();
    __syncthreads();

    // Q A-fragments, resident across the kc loop
    uint32_t qhf[4][4], qlf[4][4];
#pragma unroll
    for (int ks = 0; ks < 4; ks++) {
        const uint32_t off = (uint32_t)(wid * 16 + (lane & 15)) * AT_STRB
                           + ks * 32 + ((lane >> 4) & 1) * 16;
        ldm_x4(qhf[ks], sQh + off);
        ldm_x4(qlf[ks], sQl + off);
    }

    for (int kc = 0; kc <= qc; kc++) {
        __syncthreads();   // previous iter's K/V reads complete
        const size_t rowk = ((size_t)(b * T_SEQ + kc * 64)) * QKV3 + h * HD;
#pragma unroll
        for (int it = 0; it < 4; it++) {
            const int idx = tid + it * 128;
            const int r = idx >> 3, c = idx & 7;
            const size_t gk = rowk + DIM + (size_t)r * QKV3 + c * 8;
            const size_t gv = rowk + 2 * DIM + (size_t)r * QKV3 + c * 8;
            const uint32_t so = (uint32_t)r * AT_STRB + c * 16;
            cp16(sKh + so, qh_g + gk);
            cp16(sKl + so, ql_g + gk);
            cp16(sVh + so, qh_g + gv);
            cp16(sVl + so, ql_g + gv);
        }
        CP_COMMIT();
        CP_WAIT0();
        __syncthreads();

        // ---- S = Q K^T (3-term split) ----
        float s[8][4];
#pragma unroll
        for (int n = 0; n < 8; n++)
#pragma unroll
            for (int e = 0; e < 4; e++) s[n][e] = 0.f;

#pragma unroll
        for (int ks = 0; ks < 4; ks++) {
#pragma unroll
            for (int np = 0; np < 4; np++) {
                const uint32_t ka = (uint32_t)(np * 16 + (lane & 7) + ((lane >> 4) & 1) * 8)
                                  * AT_STRB + ks * 32 + ((lane >> 3) & 1) * 16;
                uint32_t kh[4], kl[4];
                ldm_x4(kh, sKh + ka);
                ldm_x4(kl, sKl + ka);
#pragma unroll
                for (int j = 0; j < 2; j++) {
                    const int nj = np * 2 + j;
                    mma_bf16(s[nj], qhf[ks], kh + 2 * j);
                    mma_bf16(s[nj], qhf[ks], kl + 2 * j);
                    mma_bf16(s[nj], qlf[ks], kh + 2 * j);
                }
            }
        }

        // ---- online softmax (rows: i=0 -> lane/4, i=1 -> lane/4+8) ----
#pragma unroll
        for (int n = 0; n < 8; n++)
#pragma unroll
            for (int e = 0; e < 4; e++) s[n][e] *= 0.125f;   // 1/sqrt(64)

#pragma unroll
        for (int i = 0; i < 2; i++) {
            float mx = -1e30f;
#pragma unroll
            for (int n = 0; n < 8; n++)
                mx = fmaxf(mx, fmaxf(s[n][2 * i], s[n][2 * i + 1]));
            mx = fmaxf(mx, __shfl_xor_sync(0xffffffffu, mx, 1));
            mx = fmaxf(mx, __shfl_xor_sync(0xffffffffu, mx, 2));
            const float mnew = fmaxf(mrow[i], mx);
            const float alpha = __expf(mrow[i] - mnew);
            float rs = 0.f;
#pragma unroll
            for (int n = 0; n < 8; n++) {
                s[n][2 * i]     = __expf(s[n][2 * i] - mnew);
                s[n][2 * i + 1] = __expf(s[n][2 * i + 1] - mnew);
                rs += s[n][2 * i] + s[n][2 * i + 1];
            }
            rs += __shfl_xor_sync(0xffffffffu, rs, 1);
            rs += __shfl_xor_sync(0xffffffffu, rs, 2);
            lrow[i] = lrow[i] * alpha + rs;
            mrow[i] = mnew;
#pragma unroll
            for (int n = 0; n < 8; n++) {
                o[n][2 * i]     *= alpha;
                o[n][2 * i + 1] *= alpha;
            }
        }

        // ---- P -> A-fragments (register repack, hi/lo split) ----
        uint32_t ph[4][4], pl[4][4];
#pragma unroll
        for (int t = 0; t < 4; t++) {
            splitpk(s[2 * t][0],     s[2 * t][1],     ph[t][0], pl[t][0]);
            splitpk(s[2 * t][2],     s[2 * t][3],     ph[t][1], pl[t][1]);
            splitpk(s[2 * t + 1][0], s[2 * t + 1][1], ph[t][2], pl[t][2]);
            splitpk(s[2 * t + 1][2], s[2 * t + 1][3], ph[t][3], pl[t][3]);
        }

        // ---- O += P V (3-term split; V B-frags via ldmatrix.trans) ----
        // NOTE: lane bit roles (3,4) are swapped vs the K addressing:
        // key-half selected by bit3, d-half by bit4.
#pragma unroll
        for (int t = 0; t < 4; t++) {
#pragma unroll
            for (int dp = 0; dp < 4; dp++) {
                const uint32_t va = (uint32_t)(t * 16 + (lane & 7) + ((lane >> 3) & 1) * 8)
                                  * AT_STRB + dp * 32 + ((lane >> 4) & 1) * 16;
                uint32_t vh[4], vl[4];
                ldm_x4_t(vh, sVh + va);
                ldm_x4_t(vl, sVl + va);
#pragma unroll
                for (int j = 0; j < 2; j++) {
                    const int nj = dp * 2 + j;
                    mma_bf16(o[nj], ph[t], vh + 2 * j);
                    mma_bf16(o[nj], ph[t], vl + 2 * j);
                    mma_bf16(o[nj], pl[t], vh + 2 * j);
                }
            }
        }
    }

    // ---- epilogue: normalize, hi/lo split store ----
#pragma unroll
    for (int i = 0; i < 2; i++) {
        const float inv = 1.f / lrow[i];
        const int t = qc * 64 + wid * 16 + (lane >> 2) + i * 8;
        const size_t base = ((size_t)(b * T_SEQ + t)) * DIM + h * HD + (lane & 3) * 2;
#pragma unroll
        for (int n = 0; n < 8; n++) {
            uint32_t hw, lw;
            splitpk(o[n][2 * i] * inv, o[n][2 * i + 1] * inv, hw, lw);
            *(uint32_t*)(oh_g + base + n * 8) = hw;
            *(uint32_t*)(ol_g + base + n * 8) = lw;
        }
    }
}

// ---------------------------------------------------------------------------
extern "C" void kernel_launch(void* const* d_in, const int* in_sizes, int n_in,
                              void* d_out, int out_size)
{
    (void)in_sizes; (void)n_in; (void)out_size;
    const float* x    = (const float*)d_in[0];   // [2,2048,1024]
    const float* Wqkv = (const float*)d_in[1];   // [3072,1024]
    const float* Wout = (const float*)d_in[2];   // [1024,1024]
    float* out = (float*)d_out;                  // [2,2048,1024]

    __nv_bfloat16 *xh, *xl, *wqh, *wql, *woh, *wol, *q3h, *q3l, *ah, *al;
    cudaGetSymbolAddress((void**)&xh,  g_x_hi);  cudaGetSymbolAddress((void**)&xl,  g_x_lo);
    cudaGetSymbolAddress((void**)&wqh, g_wq_hi); cudaGetSymbolAddress((void**)&wql, g_wq_lo);
    cudaGetSymbolAddress((void**)&woh, g_wo_hi); cudaGetSymbolAddress((void**)&wol, g_wo_lo);
    cudaGetSymbolAddress((void**)&q3h, g_q3_hi); cudaGetSymbolAddress((void**)&q3l, g_q3_lo);
    cudaGetSymbolAddress((void**)&ah,  g_a_hi);  cudaGetSymbolAddress((void**)&al,  g_a_lo);

    const int gemm_smem = 2 * STAGE_B;          // 81,920 B
    cudaFuncSetAttribute(gemm_mma, cudaFuncAttributeMaxDynamicSharedMemorySize, gemm_smem);
    const int attn_smem = 6 * AT_MAT;           // 55,296 B
    cudaFuncSetAttribute(attn_mma, cudaFuncAttributeMaxDynamicSharedMemorySize, attn_smem);

    // 0) split inputs to bf16 hi/lo
    cvt_split<<<(MROWS * DIM / 4 + 255) / 256, 256>>>((const float4*)x, xh, xl, MROWS * DIM / 4);
    cvt_split<<<(QKV3 * DIM / 4 + 255) / 256, 256>>>((const float4*)Wqkv, wqh, wql, QKV3 * DIM / 4);
    cvt_split<<<(DIM * DIM / 4 + 255) / 256, 256>>>((const float4*)Wout, woh, wol, DIM * DIM / 4);

    // 1) QKV projection -> split bf16 output (no fp32 intermediate)
    {
        dim3 grid(QKV3 / BN, MROWS / BM);
        gemm_mma<<<grid, 256, gemm_smem>>>(xh, xl, wqh, wql,
                                           nullptr, q3h, q3l, MROWS, QKV3, DIM, 1);
    }

    // 2) Tensor-core chunked-causal flash attention -> split bf16 output
    {
        dim3 grid(NCHUNK, NH, NB);
        attn_mma<<<grid, 128, attn_smem>>>(q3h, q3l, ah, al);
    }

    // 3) Output projection -> fp32 final
    {
        dim3 grid(DIM / BN, MROWS / BM);
        gemm_mma<<<grid, 256, gemm_smem>>>(ah, al, woh, wol,
                                           out, nullptr, nullptr, MROWS, DIM, DIM, 0);
    }
}